// round 5
// baseline (speedup 1.0000x reference)
#include <cuda_runtime.h>
#include <cstdint>

#define NB 4
#define NC 128
#define NH 192
#define NW 192
#define ND 21
#define ND2 441
#define HR 158
#define WRP 160
#define HO 156
#define WO 156

#define APAD_W 164     // floats per A row (41 quads, odd)
#define BPAD_H 200
#define BPAD_W 212     // floats per B row (53 quads, odd)

// smem layout (bytes), 3 stages
#define NSTAGE 3
#define A_ROW 656            // 164 floats
#define A_CC  (8 * A_ROW)    // 5248
#define A_STAGE (4 * A_CC)   // 20992
#define B_ROW 848            // 212 floats
#define B_CC  (8 * B_ROW)    // 6784
#define B_STAGE (4 * B_CC)   // 27136
#define A_OFF 128
#define B_OFF (A_OFF + NSTAGE * A_STAGE)        // 63104
#define SMEM_BYTES (B_OFF + NSTAGE * B_STAGE)   // 144512
#define STAGE_TX (A_STAGE + B_STAGE)            // 48128

// A tile-major: [b][yt][c][rr 8][164]
__device__ __align__(16) float g_Apad[(size_t)NB * 20 * NC * 8 * APAD_W];
// B: [b][c][200][212]
__device__ __align__(16) float g_Bpad[(size_t)NB * NC * BPAD_H * BPAD_W];
__device__ __align__(16) float g_raw [(size_t)NB * ND2 * HR * WRP];

// ---------------- Pass 0: pad/reshape inputs ----------------
__global__ void pad_A(const float* __restrict__ in1) {
    long idx = (long)blockIdx.x * blockDim.x + threadIdx.x;
    if (idx >= (long)NB * 20 * NC * 8 * APAD_W) return;
    int col = (int)(idx % APAD_W);
    long rest = idx / APAD_W;
    int rr = (int)(rest % 8);
    rest /= 8;
    int c = (int)(rest % NC);
    rest /= NC;
    int yt = (int)(rest % 20);
    int b  = (int)(rest / 20);
    g_Apad[idx] = in1[(((long)b * NC + c) * NH + yt * 8 + rr + 17) * NW + (col + 17)];
}

__global__ void pad_B(const float* __restrict__ in2) {
    long idx = (long)blockIdx.x * blockDim.x + threadIdx.x;
    if (idx >= (long)NB * NC * BPAD_H * BPAD_W) return;
    int xx = (int)(idx % BPAD_W);
    long rest = idx / BPAD_W;
    int yy = (int)(rest % BPAD_H);
    long bc = rest / BPAD_H;
    int sy = yy - 3, sx = xx - 3;
    float v = 0.f;
    if ((unsigned)sy < NH && (unsigned)sx < NW)
        v = in2[(bc * NH + sy) * NW + sx];
    g_Bpad[idx] = v;
}

// ---------------- TMA / mbarrier helpers ----------------
__device__ __forceinline__ void bulk_cp(uint32_t dst, const void* src,
                                        uint32_t bytes, uint32_t mbar) {
    asm volatile(
        "cp.async.bulk.shared::cta.global.mbarrier::complete_tx::bytes [%0], [%1], %2, [%3];"
        :: "r"(dst), "l"(src), "r"(bytes), "r"(mbar) : "memory");
}

__device__ __forceinline__ void mbar_wait(uint32_t mbar, uint32_t parity) {
    asm volatile(
        "{\n\t.reg .pred P;\n\t"
        "W_%=:\n\t"
        "mbarrier.try_wait.parity.acquire.cta.shared::cta.b64 P, [%0], %1, 10000000;\n\t"
        "@P bra D_%=;\n\t"
        "bra W_%=;\n\t"
        "D_%=:\n\t}"
        :: "r"(mbar), "r"(parity) : "memory");
}

// One stage = 1 big A copy + 4 per-channel B copies (full union dx window).
__device__ __forceinline__ void fill_stage(uint32_t sbase, int i,
                                           int b, int yt, int d) {
    const int s = i % NSTAGE;
    const uint32_t mbar = sbase + s * 8;
    const int c0 = i * 4;
    asm volatile("mbarrier.arrive.expect_tx.shared.b64 _, [%0], %1;"
                 :: "r"(mbar), "r"((uint32_t)STAGE_TX) : "memory");
    const char* srcA = (const char*)g_Apad +
        (((long)b * 20 + yt) * NC + c0) * (long)(8 * APAD_W * 4);
    bulk_cp(sbase + A_OFF + s * A_STAGE, srcA, A_STAGE, mbar);
    #pragma unroll
    for (int cc = 0; cc < 4; ++cc) {
        const char* srcB = (const char*)g_Bpad +
            (((long)b * NC + c0 + cc) * BPAD_H + yt * 8 + 20 + d) * (long)(BPAD_W * 4);
        bulk_cp(sbase + B_OFF + s * B_STAGE + cc * B_CC, srcB, B_CC, mbar);
    }
}

// ---------------- Pass 1: raw correlation ----------------
// grid (dyi, yt, b); block 320 = 2 teams x (8 rows x 20 x-groups). Team t
// computes dxi = t*10 + j (j 0..10); dxi=10 written by both (identical bits).
extern __shared__ char smem_dyn[];

__global__ __launch_bounds__(320)
void corr_pass1() {
    const int dyi = blockIdx.x;
    const int yt  = blockIdx.y;
    const int b   = blockIdx.z;
    const int d   = 2 * dyi - 20;

    const int tid  = threadIdx.x;
    const int team = (tid >= 160);
    const int t    = tid - team * 160;
    const int r    = t & 7;
    const int g    = t >> 3;
    const int x0   = g * 8;
    const int y    = yt * 8 + r;
    const int d0   = team * 10;

    char* smc = smem_dyn;
    const uint32_t sbase = (uint32_t)__cvta_generic_to_shared(smc);

    if (tid == 0) {
        #pragma unroll
        for (int s = 0; s < NSTAGE; ++s)
            asm volatile("mbarrier.init.shared.b64 [%0], 1;"
                         :: "r"(sbase + s * 8) : "memory");
        asm volatile("fence.proxy.async.shared::cta;" ::: "memory");
    }
    __syncthreads();

    if (tid == 0) {
        fill_stage(sbase, 0, b, yt, d);
        fill_stage(sbase, 1, b, yt, d);
        fill_stage(sbase, 2, b, yt, d);
    }

    float acc[11][8];
    #pragma unroll
    for (int j = 0; j < 11; ++j)
        #pragma unroll
        for (int o = 0; o < 8; ++o) acc[j][o] = 0.f;

    const int bcol = (d0 >> 1) * 16;   // 0 or 80 bytes: dx-half window offset

    for (int i = 0; i < 32; ++i) {
        const int s = i % NSTAGE;
        mbar_wait(sbase + s * 8, (i / NSTAGE) & 1);

        #pragma unroll
        for (int cc = 0; cc < 4; ++cc) {
            const float4* aq = (const float4*)(smc + A_OFF + s * A_STAGE +
                                               cc * A_CC + r * A_ROW + x0 * 4);
            const float4* bq = (const float4*)(smc + B_OFF + s * B_STAGE +
                                               cc * B_CC + r * B_ROW + bcol + x0 * 4);
            float a[8], bb[28];
            #pragma unroll
            for (int m = 0; m < 2; ++m) {
                float4 v = aq[m];
                a[4*m+0] = v.x; a[4*m+1] = v.y; a[4*m+2] = v.z; a[4*m+3] = v.w;
            }
            #pragma unroll
            for (int m = 0; m < 7; ++m) {
                float4 v = bq[m];
                bb[4*m+0] = v.x; bb[4*m+1] = v.y; bb[4*m+2] = v.z; bb[4*m+3] = v.w;
            }
            #pragma unroll
            for (int j = 0; j < 11; ++j)
                #pragma unroll
                for (int o = 0; o < 8; ++o)
                    acc[j][o] += a[o] * bb[2 * j + o];
        }
        __syncthreads();
        if (tid == 0 && i + NSTAGE < 32)
            fill_stage(sbase, i + NSTAGE, b, yt, d);
    }

    if (y < HR) {
        #pragma unroll
        for (int j = 0; j < 11; ++j) {
            int ch = dyi * ND + d0 + j;
            size_t base = (((size_t)b * ND2 + ch) * HR + y) * WRP + x0;
            *reinterpret_cast<float4*>(&g_raw[base]) =
                make_float4(acc[j][0], acc[j][1], acc[j][2], acc[j][3]);
            *reinterpret_cast<float4*>(&g_raw[base + 4]) =
                make_float4(acc[j][4], acc[j][5], acc[j][6], acc[j][7]);
        }
    }
}

// ---------------- Pass 2: 3x3 box sum / 1152, 4x4 patch per thread ----------------
__global__ void corr_pass2(float* __restrict__ out) {
    const int tid = threadIdx.x;            // 156
    const int qx = tid % 39;
    const int qy = blockIdx.y * 4 + tid / 39;
    const int ch = blockIdx.z;
    if (qy >= 39) return;
    const int i0 = qy * 4, j0 = qx * 4;
    const float inv = 1.0f / 1152.0f;

    const float* rawb = g_raw + (size_t)ch * HR * WRP;
    float w[6][4];
    #pragma unroll
    for (int rr = 0; rr < 6; ++rr) {
        const float4* p = (const float4*)(rawb + (size_t)(i0 + rr) * WRP + j0);
        float4 u = p[0], v = p[1];
        w[rr][0] = u.x + u.y + u.z;
        w[rr][1] = u.y + u.z + u.w;
        w[rr][2] = u.z + u.w + v.x;
        w[rr][3] = u.w + v.x + v.y;
    }
    float* ob = out + (size_t)ch * HO * WO + j0;
    #pragma unroll
    for (int i = 0; i < 4; ++i) {
        float4 o;
        o.x = (w[i][0] + w[i+1][0] + w[i+2][0]) * inv;
        o.y = (w[i][1] + w[i+1][1] + w[i+2][1]) * inv;
        o.z = (w[i][2] + w[i+1][2] + w[i+2][2]) * inv;
        o.w = (w[i][3] + w[i+1][3] + w[i+2][3]) * inv;
        *reinterpret_cast<float4*>(ob + (size_t)(i0 + i) * WO) = o;
    }
}

extern "C" void kernel_launch(void* const* d_in, const int* in_sizes, int n_in,
                              void* d_out, int out_size) {
    const float* in1 = (const float*)d_in[0];
    const float* in2 = (const float*)d_in[1];
    float* out = (float*)d_out;

    {
        long nA = (long)NB * 20 * NC * 8 * APAD_W;
        pad_A<<<(unsigned)((nA + 255) / 256), 256>>>(in1);
        long nBp = (long)NB * NC * BPAD_H * BPAD_W;
        pad_B<<<(unsigned)((nBp + 255) / 256), 256>>>(in2);
    }

    cudaFuncSetAttribute(corr_pass1,
                         cudaFuncAttributeMaxDynamicSharedMemorySize, SMEM_BYTES);

    dim3 g1(21, 20, 4), b1(320);
    corr_pass1<<<g1, b1, SMEM_BYTES>>>();

    dim3 g2(1, 10, NB * ND2), b2(156);
    corr_pass2<<<g2, b2>>>(out);
}